// round 5
// baseline (speedup 1.0000x reference)
#include <cuda_runtime.h>
#include <cstdint>

// ---------------------------------------------------------------------------
// DeeProBot MoE, k=1 => one-hot argmax gating; softmax(top1)==1.
//   out[n] = relu(x[n] @ W1[e] + b1[e]) @ (W2[e]@Wout) + (b2[e]@Wout + bout)
//   e = argmax(x[n] @ w_gate);  loss = closed form of the two expert counts.
//
//   fold_kernel : folded dup'd weight blob + counter/cursor reset.
//   gate_kernel : 1024 tok/block, coalesced stage, block-aggregated compaction.
//   moe_loss    : persistent warps work-steal 128-token tiles (4 tokens/thread
//                 = 2 f32x2 token-pairs), lane-major gather, warp-uniform
//                 weight LDG.128; loss fused into block 0.
// ---------------------------------------------------------------------------

#define MAXN 524288

// dup'd blob: [e][j][slot] slot0..8={W1[e][d][j]}dup, 9=Wf0 dup, 10=Wf1 dup,
// 11=b1 dup. 2*128*12 float2 = 24KB.
__device__ __align__(16) float2 g_wblob[2 * 128 * 12];
__device__ float g_bf[4];
__device__ int   g_c0 = 0, g_c1 = 0;
__device__ int   g_tile = 0;
__device__ int   g_idx0[MAXN];
__device__ int   g_idx1[MAXN];

// ---------------- packed f32x2 helpers ----------------
__device__ __forceinline__ unsigned long long fma2(unsigned long long a,
                                                   unsigned long long b,
                                                   unsigned long long c) {
    unsigned long long d;
    asm("fma.rn.f32x2 %0, %1, %2, %3;" : "=l"(d) : "l"(a), "l"(b), "l"(c));
    return d;
}
__device__ __forceinline__ unsigned long long pack2(float a, float b) {
    unsigned long long r;
    asm("mov.b64 %0, {%1, %2};" : "=l"(r) : "f"(a), "f"(b));
    return r;
}
__device__ __forceinline__ float2 unpack2(unsigned long long v) {
    float2 r;
    asm("mov.b64 {%0, %1}, %2;" : "=f"(r.x), "=f"(r.y) : "l"(v));
    return r;
}
__device__ __forceinline__ unsigned long long relu2(unsigned long long h) {
    float2 t = unpack2(h);
    return pack2(fmaxf(t.x, 0.0f), fmaxf(t.y, 0.0f));
}

// ---------------------------------------------------------------------------
// fold_kernel: dup'd blob + folded output bias + state reset.
// ---------------------------------------------------------------------------
__global__ void __launch_bounds__(256) fold_kernel(
        const float* __restrict__ W1, const float* __restrict__ b1,
        const float* __restrict__ W2, const float* __restrict__ b2,
        const float* __restrict__ Wout, const float* __restrict__ bout) {
    const int tid = threadIdx.x;
    for (int idx = tid; idx < 3072; idx += 256) {
        int e    = idx / 1536;
        int j    = (idx / 12) & 127;
        int slot = idx % 12;
        float v;
        if (slot < 9) {
            v = W1[(e * 9 + slot) * 128 + j];
        } else if (slot < 11) {
            int o = slot - 9;
            float s = 0.0f;
            #pragma unroll
            for (int m = 0; m < 32; ++m)
                s = fmaf(W2[(e * 128 + j) * 32 + m], Wout[m * 2 + o], s);
            v = s;
        } else {
            v = b1[e * 128 + j];
        }
        g_wblob[idx] = make_float2(v, v);
    }
    if (tid < 4) {
        int e = tid >> 1, o = tid & 1;
        float s = bout[o];
        #pragma unroll
        for (int m = 0; m < 32; ++m)
            s = fmaf(b2[e * 32 + m], Wout[m * 2 + o], s);
        g_bf[tid] = s;
    }
    if (tid == 0) { g_c0 = 0; g_c1 = 0; g_tile = 0; }
}

// ---------------------------------------------------------------------------
// gate_kernel: 1024 tokens per 256-thread block, block-aggregated compaction.
// ---------------------------------------------------------------------------
__global__ void __launch_bounds__(256) gate_kernel(const float* __restrict__ x,
                                                   const float* __restrict__ wg,
                                                   int N) {
    __shared__ float sx[9216];            // 1024 tokens * 9
    __shared__ int swc0[8], swc1[8];
    __shared__ int spf0[8], spf1[8];
    __shared__ int sbase0, sbase1;

    const int tid  = threadIdx.x;
    const int tok0 = blockIdx.x * 1024;
    const int navail = min(1024, N - tok0);
    const int nflt = navail * 9;

    {
        const float4* xb = reinterpret_cast<const float4*>(x + (size_t)tok0 * 9);
        float4* s4 = reinterpret_cast<float4*>(sx);
        int nf4 = nflt >> 2;
        for (int i = tid; i < nf4; i += 256) s4[i] = xb[i];
        for (int i = (nf4 << 2) + tid; i < nflt; i += 256)
            sx[i] = x[(size_t)tok0 * 9 + i];
    }
    float wgr[18];
    #pragma unroll
    for (int i = 0; i < 18; ++i) wgr[i] = __ldg(wg + i);
    __syncthreads();

    const int lane = tid & 31, w = tid >> 5;
    unsigned m0[4], m1[4];

    #pragma unroll
    for (int p = 0; p < 4; ++p) {
        int tl = tid + 256 * p;           // stride-9 LDS: conflict-free
        bool valid = tl < navail;
        float l0 = 0.0f, l1 = 0.0f;
        #pragma unroll
        for (int d = 0; d < 9; ++d) {
            float v = sx[tl * 9 + d];
            l0 = fmaf(v, wgr[2 * d], l0);
            l1 = fmaf(v, wgr[2 * d + 1], l1);
        }
        unsigned mv = __ballot_sync(0xffffffffu, valid);
        m1[p] = __ballot_sync(0xffffffffu, valid && (l1 > l0));
        m0[p] = mv & ~m1[p];
    }
    if (lane == 0) {
        int c0 = 0, c1 = 0;
        #pragma unroll
        for (int p = 0; p < 4; ++p) { c0 += __popc(m0[p]); c1 += __popc(m1[p]); }
        swc0[w] = c0; swc1[w] = c1;
    }
    __syncthreads();
    if (tid == 0) {
        int t0 = 0, t1 = 0;
        #pragma unroll
        for (int i = 0; i < 8; ++i) {
            spf0[i] = t0; t0 += swc0[i];
            spf1[i] = t1; t1 += swc1[i];
        }
        sbase0 = atomicAdd(&g_c0, t0);
        sbase1 = atomicAdd(&g_c1, t1);
    }
    __syncthreads();

    int off0 = sbase0 + spf0[w];
    int off1 = sbase1 + spf1[w];
    const unsigned below = (1u << lane) - 1u;
    #pragma unroll
    for (int p = 0; p < 4; ++p) {
        int t = tok0 + tid + 256 * p;
        if ((m1[p] >> lane) & 1u) g_idx1[off1 + __popc(m1[p] & below)] = t;
        if ((m0[p] >> lane) & 1u) g_idx0[off0 + __popc(m0[p] & below)] = t;
        off0 += __popc(m0[p]);
        off1 += __popc(m1[p]);
    }
}

// ---------------------------------------------------------------------------
// moe_loss: persistent warps work-steal 128-token tiles of a single expert.
// Per tile: 4 tokens/thread = 2 lane-major f32x2 token-pairs.
// ---------------------------------------------------------------------------
__global__ void __launch_bounds__(256, 2) moe_loss(const float* __restrict__ x,
                                                   float* __restrict__ out,
                                                   int N, int out_size) {
    const int c0 = g_c0, c1 = g_c1;

    if (blockIdx.x == 0 && threadIdx.x == 0 && out_size > 2 * N) {
        double cc1  = (double)c1;
        double cc0  = (double)N - cc1;
        double mean = 0.5 * (cc0 + cc1);
        double d    = cc0 - cc1;
        double cv   = (0.5 * d * d) / (mean * mean + 1e-10);
        out[out_size - 1] = (float)(0.02 * cv);
    }

    const int nt0    = (c0 + 127) >> 7;
    const int nt1    = (c1 + 127) >> 7;
    const int ntiles = nt0 + nt1;
    const int lane   = threadIdx.x & 31;
    float2* out2 = reinterpret_cast<float2*>(out);

    for (;;) {
        int tile;
        if (lane == 0) tile = atomicAdd(&g_tile, 1);
        tile = __shfl_sync(0xffffffffu, tile, 0);
        if (tile >= ntiles) break;

        const int* __restrict__ list;
        int start, cnt, e;
        if (tile < nt0) { list = g_idx0; e = 0; start = tile << 7;         cnt = c0; }
        else            { list = g_idx1; e = 1; start = (tile - nt0) << 7; cnt = c1; }

        // gather 4 tokens as 2 lane-major token-pairs
        unsigned long long x2[2][9];
        #pragma unroll
        for (int q = 0; q < 2; ++q) {
            int ia = min(start + 64 * q +      lane, cnt - 1);
            int ib = min(start + 64 * q + 32 + lane, cnt - 1);
            int ta = __ldg(list + ia);
            int tb = __ldg(list + ib);
            const float* xa = x + (size_t)ta * 9;
            const float* xb = x + (size_t)tb * 9;
            #pragma unroll
            for (int d = 0; d < 9; ++d)
                x2[q][d] = pack2(__ldg(xa + d), __ldg(xb + d));
        }

        const ulonglong2* __restrict__ wb =
            reinterpret_cast<const ulonglong2*>(g_wblob) + e * 768;

        unsigned long long a00 = 0ull, a01 = 0ull;
        unsigned long long a10 = 0ull, a11 = 0ull;

        #pragma unroll 2
        for (int j = 0; j < 128; ++j) {
            const ulonglong2* row = wb + j * 6;
            ulonglong2 w0 = row[0], w1 = row[1], w2 = row[2];
            ulonglong2 w3 = row[3], w4 = row[4], w5 = row[5];
            // w0={d0,d1} w1={d2,d3} w2={d4,d5} w3={d6,d7} w4={d8,Wf0} w5={Wf1,b1}
            {
                unsigned long long h = w5.y;
                h = fma2(x2[0][0], w0.x, h);
                h = fma2(x2[0][1], w0.y, h);
                h = fma2(x2[0][2], w1.x, h);
                h = fma2(x2[0][3], w1.y, h);
                h = fma2(x2[0][4], w2.x, h);
                h = fma2(x2[0][5], w2.y, h);
                h = fma2(x2[0][6], w3.x, h);
                h = fma2(x2[0][7], w3.y, h);
                h = fma2(x2[0][8], w4.x, h);
                h = relu2(h);
                a00 = fma2(h, w4.y, a00);
                a01 = fma2(h, w5.x, a01);
            }
            {
                unsigned long long h = w5.y;
                h = fma2(x2[1][0], w0.x, h);
                h = fma2(x2[1][1], w0.y, h);
                h = fma2(x2[1][2], w1.x, h);
                h = fma2(x2[1][3], w1.y, h);
                h = fma2(x2[1][4], w2.x, h);
                h = fma2(x2[1][5], w2.y, h);
                h = fma2(x2[1][6], w3.x, h);
                h = fma2(x2[1][7], w3.y, h);
                h = fma2(x2[1][8], w4.x, h);
                h = relu2(h);
                a10 = fma2(h, w4.y, a10);
                a11 = fma2(h, w5.x, a11);
            }
        }

        const float bf0 = g_bf[2 * e], bf1 = g_bf[2 * e + 1];
        {
            float2 o0 = unpack2(a00), o1 = unpack2(a01);
            int ia = start + lane, ib = ia + 32;
            if (ia < cnt) out2[__ldg(list + ia)] = make_float2(o0.x + bf0, o1.x + bf1);
            if (ib < cnt) out2[__ldg(list + ib)] = make_float2(o0.y + bf0, o1.y + bf1);
        }
        {
            float2 o0 = unpack2(a10), o1 = unpack2(a11);
            int ia = start + 64 + lane, ib = ia + 32;
            if (ia < cnt) out2[__ldg(list + ia)] = make_float2(o0.x + bf0, o1.x + bf1);
            if (ib < cnt) out2[__ldg(list + ib)] = make_float2(o0.y + bf0, o1.y + bf1);
        }
    }
}

// ---------------------------------------------------------------------------
// Inputs: num_prop, cat_prop, w_gate, W1, b1, W2, b2, Wout, bout, k
// ---------------------------------------------------------------------------
extern "C" void kernel_launch(void* const* d_in, const int* in_sizes, int n_in,
                              void* d_out, int out_size) {
    const float* x    = (const float*)d_in[0];
    const float* wg   = (const float*)d_in[2];
    const float* W1   = (const float*)d_in[3];
    const float* b1   = (const float*)d_in[4];
    const float* W2   = (const float*)d_in[5];
    const float* b2   = (const float*)d_in[6];
    const float* Wout = (const float*)d_in[7];
    const float* bout = (const float*)d_in[8];
    float* out = (float*)d_out;

    int N = in_sizes[0] / 9;

    fold_kernel<<<1, 256>>>(W1, b1, W2, b2, Wout, bout);
    gate_kernel<<<(N + 1023) / 1024, 256>>>(x, wg, N);
    moe_loss<<<296, 256>>>(x, out, N, out_size);
}

// round 6
// speedup vs baseline: 1.1154x; 1.1154x over previous
#include <cuda_runtime.h>
#include <cstdint>

// ---------------------------------------------------------------------------
// DeeProBot MoE, k=1 => one-hot argmax gating; softmax(top1)==1.
//   out[n] = relu(x[n] @ W1[e] + b1[e]) @ (W2[e]@Wout) + (b2[e]@Wout + bout)
//   e = argmax(x[n] @ w_gate);  loss = closed form of the two expert counts.
//
//   fold_kernel : folded dup'd weight blob + counter reset.
//   gate_kernel : gating + compaction + PRE-GATHER of x into expert-compacted
//                 SoA buffers (coalesced writes) so moe reads are coalesced.
//   moe_loss    : warp = 256 compacted tokens of one expert; 8 tokens/thread
//                 as 4 f32x2 pairs of ADJACENT compacted tokens (LDG.64 SoA
//                 loads, no packing); warp-uniform weight LDG.128; loss fused.
// ---------------------------------------------------------------------------

#define MAXN 524288
#define NP   (MAXN + 256)     // padded row stride for SoA / tail-safe reads

__device__ __align__(16) float2 g_wblob[2 * 128 * 12];  // dup'd folded weights
__device__ float g_bf[4];
__device__ int   g_c0 = 0, g_c1 = 0;
__device__ int   g_idx0[NP];
__device__ int   g_idx1[NP];
__device__ float g_xg0[9 * NP];   // SoA: [d][pos], expert-0 compacted
__device__ float g_xg1[9 * NP];   // SoA: [d][pos], expert-1 compacted

// ---------------- packed f32x2 helpers ----------------
__device__ __forceinline__ unsigned long long fma2(unsigned long long a,
                                                   unsigned long long b,
                                                   unsigned long long c) {
    unsigned long long d;
    asm("fma.rn.f32x2 %0, %1, %2, %3;" : "=l"(d) : "l"(a), "l"(b), "l"(c));
    return d;
}
__device__ __forceinline__ float2 unpack2(unsigned long long v) {
    float2 r;
    asm("mov.b64 {%0, %1}, %2;" : "=f"(r.x), "=f"(r.y) : "l"(v));
    return r;
}
__device__ __forceinline__ unsigned long long pack2(float a, float b) {
    unsigned long long r;
    asm("mov.b64 %0, {%1, %2};" : "=l"(r) : "f"(a), "f"(b));
    return r;
}
__device__ __forceinline__ unsigned long long relu2(unsigned long long h) {
    float2 t = unpack2(h);
    return pack2(fmaxf(t.x, 0.0f), fmaxf(t.y, 0.0f));
}

// ---------------------------------------------------------------------------
// fold_kernel: dup'd blob + folded output bias + counter reset.
// ---------------------------------------------------------------------------
__global__ void __launch_bounds__(256) fold_kernel(
        const float* __restrict__ W1, const float* __restrict__ b1,
        const float* __restrict__ W2, const float* __restrict__ b2,
        const float* __restrict__ Wout, const float* __restrict__ bout) {
    const int tid = threadIdx.x;
    for (int idx = tid; idx < 3072; idx += 256) {
        int e    = idx / 1536;
        int j    = (idx / 12) & 127;
        int slot = idx % 12;
        float v;
        if (slot < 9) {
            v = W1[(e * 9 + slot) * 128 + j];
        } else if (slot < 11) {
            int o = slot - 9;
            float s = 0.0f;
            #pragma unroll
            for (int m = 0; m < 32; ++m)
                s = fmaf(W2[(e * 128 + j) * 32 + m], Wout[m * 2 + o], s);
            v = s;
        } else {
            v = b1[e * 128 + j];
        }
        g_wblob[idx] = make_float2(v, v);
    }
    if (tid < 4) {
        int e = tid >> 1, o = tid & 1;
        float s = bout[o];
        #pragma unroll
        for (int m = 0; m < 32; ++m)
            s = fmaf(b2[e * 32 + m], Wout[m * 2 + o], s);
        g_bf[tid] = s;
    }
    if (tid == 0) { g_c0 = 0; g_c1 = 0; }
}

// ---------------------------------------------------------------------------
// gate_kernel: 1024 tokens/block. Gating, compaction, and x pre-gather into
// expert-compacted SoA (writes are warp-coalesced: consecutive lanes go to
// consecutive compacted slots).
// ---------------------------------------------------------------------------
__global__ void __launch_bounds__(256) gate_kernel(const float* __restrict__ x,
                                                   const float* __restrict__ wg,
                                                   int N) {
    __shared__ float sx[9216];            // 1024 tokens * 9
    __shared__ int swc0[8], swc1[8];
    __shared__ int spf0[8], spf1[8];
    __shared__ int sbase0, sbase1;

    const int tid  = threadIdx.x;
    const int tok0 = blockIdx.x * 1024;
    const int navail = min(1024, N - tok0);
    const int nflt = navail * 9;

    {
        const float4* xb = reinterpret_cast<const float4*>(x + (size_t)tok0 * 9);
        float4* s4 = reinterpret_cast<float4*>(sx);
        int nf4 = nflt >> 2;
        for (int i = tid; i < nf4; i += 256) s4[i] = xb[i];
        for (int i = (nf4 << 2) + tid; i < nflt; i += 256)
            sx[i] = x[(size_t)tok0 * 9 + i];
    }
    float wgr[18];
    #pragma unroll
    for (int i = 0; i < 18; ++i) wgr[i] = __ldg(wg + i);
    __syncthreads();

    const int lane = tid & 31, w = tid >> 5;
    unsigned m0[4], m1[4];

    #pragma unroll
    for (int p = 0; p < 4; ++p) {
        int tl = tid + 256 * p;           // stride-9 LDS: conflict-free
        bool valid = tl < navail;
        float l0 = 0.0f, l1 = 0.0f;
        #pragma unroll
        for (int d = 0; d < 9; ++d) {
            float v = sx[tl * 9 + d];
            l0 = fmaf(v, wgr[2 * d], l0);
            l1 = fmaf(v, wgr[2 * d + 1], l1);
        }
        unsigned mv = __ballot_sync(0xffffffffu, valid);
        m1[p] = __ballot_sync(0xffffffffu, valid && (l1 > l0));
        m0[p] = mv & ~m1[p];
    }
    if (lane == 0) {
        int c0 = 0, c1 = 0;
        #pragma unroll
        for (int p = 0; p < 4; ++p) { c0 += __popc(m0[p]); c1 += __popc(m1[p]); }
        swc0[w] = c0; swc1[w] = c1;
    }
    __syncthreads();
    if (tid == 0) {
        int t0 = 0, t1 = 0;
        #pragma unroll
        for (int i = 0; i < 8; ++i) {
            spf0[i] = t0; t0 += swc0[i];
            spf1[i] = t1; t1 += swc1[i];
        }
        sbase0 = atomicAdd(&g_c0, t0);
        sbase1 = atomicAdd(&g_c1, t1);
    }
    __syncthreads();

    int off0 = sbase0 + spf0[w];
    int off1 = sbase1 + spf1[w];
    const unsigned below = (1u << lane) - 1u;
    #pragma unroll
    for (int p = 0; p < 4; ++p) {
        int tl = tid + 256 * p;
        int t  = tok0 + tl;
        if ((m1[p] >> lane) & 1u) {
            int pos = off1 + __popc(m1[p] & below);
            g_idx1[pos] = t;
            #pragma unroll
            for (int d = 0; d < 9; ++d)
                g_xg1[d * NP + pos] = sx[tl * 9 + d];
        }
        if ((m0[p] >> lane) & 1u) {
            int pos = off0 + __popc(m0[p] & below);
            g_idx0[pos] = t;
            #pragma unroll
            for (int d = 0; d < 9; ++d)
                g_xg0[d * NP + pos] = sx[tl * 9 + d];
        }
        off0 += __popc(m0[p]);
        off1 += __popc(m1[p]);
    }
}

// ---------------------------------------------------------------------------
// moe_loss: flat warp->tile map over fixed grid; warp = 256 tokens of one
// expert; thread = 4 pairs of adjacent compacted tokens (SoA LDG.64 loads).
// Loss fused into block 0.
// ---------------------------------------------------------------------------
__global__ void __launch_bounds__(256, 2) moe_loss(float* __restrict__ out,
                                                   int N, int out_size) {
    const int c0 = g_c0, c1 = g_c1;

    if (blockIdx.x == 0 && threadIdx.x == 0 && out_size > 2 * N) {
        double cc1  = (double)c1;
        double cc0  = (double)N - cc1;
        double mean = 0.5 * (cc0 + cc1);
        double d    = cc0 - cc1;
        double cv   = (0.5 * d * d) / (mean * mean + 1e-10);
        out[out_size - 1] = (float)(0.02 * cv);
    }

    const int W    = blockIdx.x * 8 + (threadIdx.x >> 5);
    const int lane = threadIdx.x & 31;
    const int nt0  = (c0 + 255) >> 8;
    const int nt1  = (c1 + 255) >> 8;
    if (W >= nt0 + nt1) return;

    const int* __restrict__ list;
    const float* __restrict__ xg;
    int start, cnt, e;
    if (W < nt0) { list = g_idx0; xg = g_xg0; e = 0; start = W << 8;         cnt = c0; }
    else         { list = g_idx1; xg = g_xg1; e = 1; start = (W - nt0) << 8; cnt = c1; }

    // 4 pairs of adjacent compacted tokens: coalesced LDG.64 from SoA rows
    unsigned long long x2[4][9];
    #pragma unroll
    for (int q = 0; q < 4; ++q) {
        int idx = start + 64 * q + 2 * lane;   // even -> 8B aligned
        #pragma unroll
        for (int d = 0; d < 9; ++d)
            x2[q][d] = __ldg(reinterpret_cast<const unsigned long long*>(
                                 xg + (size_t)d * NP + idx));
    }

    const ulonglong2* __restrict__ wb =
        reinterpret_cast<const ulonglong2*>(g_wblob) + e * 768;

    unsigned long long acc[4][2];
    #pragma unroll
    for (int q = 0; q < 4; ++q) { acc[q][0] = 0ull; acc[q][1] = 0ull; }

    #pragma unroll 2
    for (int j = 0; j < 128; ++j) {
        const ulonglong2* row = wb + j * 6;
        ulonglong2 w0 = row[0], w1 = row[1], w2 = row[2];
        ulonglong2 w3 = row[3], w4 = row[4], w5 = row[5];
        // w0={d0,d1} w1={d2,d3} w2={d4,d5} w3={d6,d7} w4={d8,Wf0} w5={Wf1,b1}
        #pragma unroll
        for (int q = 0; q < 4; ++q) {
            unsigned long long h = w5.y;        // b1 dup
            h = fma2(x2[q][0], w0.x, h);
            h = fma2(x2[q][1], w0.y, h);
            h = fma2(x2[q][2], w1.x, h);
            h = fma2(x2[q][3], w1.y, h);
            h = fma2(x2[q][4], w2.x, h);
            h = fma2(x2[q][5], w2.y, h);
            h = fma2(x2[q][6], w3.x, h);
            h = fma2(x2[q][7], w3.y, h);
            h = fma2(x2[q][8], w4.x, h);
            h = relu2(h);
            acc[q][0] = fma2(h, w4.y, acc[q][0]);   // Wf o=0
            acc[q][1] = fma2(h, w5.x, acc[q][1]);   // Wf o=1
        }
    }

    const float bf0 = g_bf[2 * e], bf1 = g_bf[2 * e + 1];
    float2* out2 = reinterpret_cast<float2*>(out);

    #pragma unroll
    for (int q = 0; q < 4; ++q) {
        float2 o0 = unpack2(acc[q][0]);   // {tokA, tokB} out-dim 0
        float2 o1 = unpack2(acc[q][1]);   // {tokA, tokB} out-dim 1
        int i0 = start + 64 * q + 2 * lane;
        int i1 = i0 + 1;
        if (i0 < cnt) out2[__ldg(list + i0)] = make_float2(o0.x + bf0, o1.x + bf1);
        if (i1 < cnt) out2[__ldg(list + i1)] = make_float2(o0.y + bf0, o1.y + bf1);
    }
}

// ---------------------------------------------------------------------------
// Inputs: num_prop, cat_prop, w_gate, W1, b1, W2, b2, Wout, bout, k
// ---------------------------------------------------------------------------
extern "C" void kernel_launch(void* const* d_in, const int* in_sizes, int n_in,
                              void* d_out, int out_size) {
    const float* x    = (const float*)d_in[0];
    const float* wg   = (const float*)d_in[2];
    const float* W1   = (const float*)d_in[3];
    const float* b1   = (const float*)d_in[4];
    const float* W2   = (const float*)d_in[5];
    const float* b2   = (const float*)d_in[6];
    const float* Wout = (const float*)d_in[7];
    const float* bout = (const float*)d_in[8];
    float* out = (float*)d_out;

    int N = in_sizes[0] / 9;

    fold_kernel<<<1, 256>>>(W1, b1, W2, b2, Wout, bout);
    gate_kernel<<<(N + 1023) / 1024, 256>>>(x, wg, N);
    moe_loss<<<296, 256>>>(out, N, out_size);   // 2368 warps >= max 2050 tiles
}